// round 2
// baseline (speedup 1.0000x reference)
#include <cuda_runtime.h>
#include <math.h>

#define DD 6
#define SEQ 128

__global__ __launch_bounds__(128) void block_ffn_kernel(
    const float* __restrict__ x,
    const float* __restrict__ ln1_w, const float* __restrict__ ln1_b,
    const float* __restrict__ wqkv,  const float* __restrict__ bqkv,
    const float* __restrict__ wo,    const float* __restrict__ bo,
    const float* __restrict__ ln2_w, const float* __restrict__ ln2_b,
    const float* __restrict__ w1,    const float* __restrict__ b1,
    const float* __restrict__ w2,    const float* __restrict__ b2,
    float* __restrict__ out)
{
    __shared__ float s_kv[SEQ * 12];     // per token: k[0..5], v[0..5]
    __shared__ float s_w[276];

    float* s_wqkv = s_w;          // 108  [6][18]
    float* s_bqkv = s_w + 108;    // 18
    float* s_wo   = s_w + 126;    // 36   [6][6]
    float* s_bo   = s_w + 162;    // 6
    float* s_w1   = s_w + 168;    // 36
    float* s_b1   = s_w + 204;    // 6
    float* s_w2   = s_w + 210;    // 36
    float* s_b2   = s_w + 246;    // 6
    float* s_l1w  = s_w + 252;    // 6
    float* s_l1b  = s_w + 258;    // 6
    float* s_l2w  = s_w + 264;    // 6
    float* s_l2b  = s_w + 270;    // 6

    const int t = threadIdx.x;

    // ---- stage weights to smem ----
    if (t < 108) s_wqkv[t] = wqkv[t];
    if (t < 18)  s_bqkv[t] = bqkv[t];
    if (t < 36) {
        s_wo[t] = wo[t];
        s_w1[t] = w1[t];
        s_w2[t] = w2[t];
    }
    if (t < DD) {
        s_bo[t]  = bo[t];
        s_b1[t]  = b1[t];
        s_b2[t]  = b2[t];
        s_l1w[t] = ln1_w[t];
        s_l1b[t] = ln1_b[t];
        s_l2w[t] = ln2_w[t];
        s_l2b[t] = ln2_b[t];
    }

    // ---- load my token's x ----
    const long base = ((long)blockIdx.x * SEQ + t) * DD;
    float xv[DD];
#pragma unroll
    for (int j = 0; j < DD; ++j) xv[j] = x[base + j];

    // ---- LN1 ----
    float mean = 0.f;
#pragma unroll
    for (int j = 0; j < DD; ++j) mean += xv[j];
    mean *= (1.f / DD);
    float var = 0.f;
#pragma unroll
    for (int j = 0; j < DD; ++j) { float d = xv[j] - mean; var = fmaf(d, d, var); }
    float rstd = rsqrtf(var * (1.f / DD) + 1e-5f);

    __syncthreads();   // weights visible

    float h[DD];
#pragma unroll
    for (int j = 0; j < DD; ++j)
        h[j] = fmaf((xv[j] - mean) * rstd, s_l1w[j], s_l1b[j]);

    // ---- QKV projection ----
    float q[DD];
#pragma unroll
    for (int j = 0; j < DD; ++j) {
        float a = s_bqkv[j];
#pragma unroll
        for (int i = 0; i < DD; ++i) a = fmaf(h[i], s_wqkv[i * 18 + j], a);
        q[j] = a * 0.40824829046386307f;   // fold 1/sqrt(D) into q
    }
#pragma unroll
    for (int j = 0; j < 12; ++j) {
        float a = s_bqkv[6 + j];
#pragma unroll
        for (int i = 0; i < DD; ++i) a = fmaf(h[i], s_wqkv[i * 18 + 6 + j], a);
        s_kv[t * 12 + j] = a;
    }

    __syncthreads();   // all K/V visible

    // ---- causal attention, max-free online softmax (scores bounded) ----
    float l = 0.f;
    float acc[DD];
#pragma unroll
    for (int j = 0; j < DD; ++j) acc[j] = 0.f;

    for (int j = 0; j <= t; ++j) {
        const float4* kp = (const float4*)(s_kv + j * 12);
        float4 a = kp[0];            // k0..k3
        float4 b = kp[1];            // k4,k5,v0,v1
        float4 c = kp[2];            // v2..v5
        float s = fmaf(q[0], a.x,
                  fmaf(q[1], a.y,
                  fmaf(q[2], a.z,
                  fmaf(q[3], a.w,
                  fmaf(q[4], b.x, q[5] * b.y)))));
        float p = __expf(s);
        l += p;
        acc[0] = fmaf(p, b.z, acc[0]);
        acc[1] = fmaf(p, b.w, acc[1]);
        acc[2] = fmaf(p, c.x, acc[2]);
        acc[3] = fmaf(p, c.y, acc[3]);
        acc[4] = fmaf(p, c.z, acc[4]);
        acc[5] = fmaf(p, c.w, acc[5]);
    }
    float inv = 1.0f / l;
    float o[DD];
#pragma unroll
    for (int j = 0; j < DD; ++j) o[j] = acc[j] * inv;

    // ---- output projection + residual ----
    float y[DD];
#pragma unroll
    for (int j = 0; j < DD; ++j) {
        float a = s_bo[j];
#pragma unroll
        for (int i = 0; i < DD; ++i) a = fmaf(o[i], s_wo[i * 6 + j], a);
        y[j] = xv[j] + a;
    }

    // ---- LN2 ----
    float mean2 = 0.f;
#pragma unroll
    for (int j = 0; j < DD; ++j) mean2 += y[j];
    mean2 *= (1.f / DD);
    float var2 = 0.f;
#pragma unroll
    for (int j = 0; j < DD; ++j) { float d = y[j] - mean2; var2 = fmaf(d, d, var2); }
    float rstd2 = rsqrtf(var2 * (1.f / DD) + 1e-5f);
    float h2[DD];
#pragma unroll
    for (int j = 0; j < DD; ++j)
        h2[j] = fmaf((y[j] - mean2) * rstd2, s_l2w[j], s_l2b[j]);

    // ---- FFN: gelu(h2@w1+b1)@w2+b2, residual ----
    float g[DD];
#pragma unroll
    for (int j = 0; j < DD; ++j) {
        float a = s_b1[j];
#pragma unroll
        for (int i = 0; i < DD; ++i) a = fmaf(h2[i], s_w1[i * 6 + j], a);
        g[j] = a * normcdff(a);            // exact gelu: x * Phi(x)
    }
#pragma unroll
    for (int j = 0; j < DD; ++j) {
        float a = s_b2[j];
#pragma unroll
        for (int i = 0; i < DD; ++i) a = fmaf(g[i], s_w2[i * 6 + j], a);
        out[base + j] = y[j] + a;
    }
}

extern "C" void kernel_launch(void* const* d_in, const int* in_sizes, int n_in,
                              void* d_out, int out_size) {
    const float* x     = (const float*)d_in[0];
    const float* ln1_w = (const float*)d_in[1];
    const float* ln1_b = (const float*)d_in[2];
    const float* wqkv  = (const float*)d_in[3];
    const float* bqkv  = (const float*)d_in[4];
    const float* wo    = (const float*)d_in[5];
    const float* bo    = (const float*)d_in[6];
    const float* ln2_w = (const float*)d_in[7];
    const float* ln2_b = (const float*)d_in[8];
    const float* w1    = (const float*)d_in[9];
    const float* b1    = (const float*)d_in[10];
    const float* w2    = (const float*)d_in[11];
    const float* b2    = (const float*)d_in[12];
    float* out = (float*)d_out;

    const int B = in_sizes[0] / (SEQ * DD);   // 8192
    block_ffn_kernel<<<B, SEQ>>>(x, ln1_w, ln1_b, wqkv, bqkv, wo, bo,
                                 ln2_w, ln2_b, w1, b1, w2, b2, out);
}

// round 4
// speedup vs baseline: 1.1179x; 1.1179x over previous
#include <cuda_runtime.h>
#include <math.h>

#define DD 6
#define SEQ 128
typedef unsigned long long u64;

// ---- f32x2 packed math (sm_100+; ptxas never auto-fuses these) ----
__device__ __forceinline__ u64 pack2(float lo, float hi) {
    u64 r; asm("mov.b64 %0, {%1, %2};" : "=l"(r) : "f"(lo), "f"(hi)); return r;
}
__device__ __forceinline__ void unpack2(u64 v, float& lo, float& hi) {
    asm("mov.b64 {%0, %1}, %2;" : "=f"(lo), "=f"(hi) : "l"(v));
}
__device__ __forceinline__ u64 ffma2(u64 a, u64 b, u64 c) {
    u64 d; asm("fma.rn.f32x2 %0, %1, %2, %3;" : "=l"(d) : "l"(a), "l"(b), "l"(c)); return d;
}
__device__ __forceinline__ u64 fmul2(u64 a, u64 b) {
    u64 d; asm("mul.rn.f32x2 %0, %1, %2;" : "=l"(d) : "l"(a), "l"(b)); return d;
}
__device__ __forceinline__ u64 fadd2(u64 a, u64 b) {
    u64 d; asm("add.rn.f32x2 %0, %1, %2;" : "=l"(d) : "l"(a), "l"(b)); return d;
}
__device__ __forceinline__ float ex2f(float x) {
    float y; asm("ex2.approx.f32 %0, %1;" : "=f"(y) : "f"(x)); return y;
}
__device__ __forceinline__ float rcpf(float x) {
    float y; asm("rcp.approx.f32 %0, %1;" : "=f"(y) : "f"(x)); return y;
}

// dot over D=6: q pre-duplicated (q_i,q_i); K lanes carry (key 2j, key 2j+1)
__device__ __forceinline__ u64 dot6(const u64* q, ulonglong2 K0, ulonglong2 K1, ulonglong2 K2) {
    return ffma2(q[0], K0.x,
           ffma2(q[1], K0.y,
           ffma2(q[2], K1.x,
           ffma2(q[3], K1.y,
           ffma2(q[4], K2.x,
           fmul2(q[5], K2.y))))));
}

// out-proj + residual + LN2 + FFN + residual for one token
__device__ __forceinline__ void epilogue(
    const float* o, const float* xv,
    const float* s_wo, const float* s_bo,
    const float* s_l2w, const float* s_l2b,
    const float* s_w1, const float* s_b1,
    const float* s_w2, const float* s_b2,
    float* res)
{
    float y[DD];
#pragma unroll
    for (int d = 0; d < DD; ++d) {
        float a = s_bo[d];
#pragma unroll
        for (int i = 0; i < DD; ++i) a = fmaf(o[i], s_wo[i * 6 + d], a);
        y[d] = xv[d] + a;
    }
    float m = 0.f;
#pragma unroll
    for (int d = 0; d < DD; ++d) m += y[d];
    m *= (1.f / DD);
    float v = 0.f;
#pragma unroll
    for (int d = 0; d < DD; ++d) { float t = y[d] - m; v = fmaf(t, t, v); }
    float r = rsqrtf(v * (1.f / DD) + 1e-5f);
    float h2[DD];
#pragma unroll
    for (int d = 0; d < DD; ++d)
        h2[d] = fmaf((y[d] - m) * r, s_l2w[d], s_l2b[d]);
    float g[DD];
#pragma unroll
    for (int d = 0; d < DD; ++d) {
        float a = s_b1[d];
#pragma unroll
        for (int i = 0; i < DD; ++i) a = fmaf(h2[i], s_w1[i * 6 + d], a);
        g[d] = a * normcdff(a);           // exact gelu
    }
#pragma unroll
    for (int d = 0; d < DD; ++d) {
        float a = s_b2[d];
#pragma unroll
        for (int i = 0; i < DD; ++i) a = fmaf(g[i], s_w2[i * 6 + d], a);
        res[d] = y[d] + a;
    }
}

__global__ __launch_bounds__(128) void block_ffn_kernel(
    const float* __restrict__ x,
    const float* __restrict__ ln1_w, const float* __restrict__ ln1_b,
    const float* __restrict__ wqkv,  const float* __restrict__ bqkv,
    const float* __restrict__ wo,    const float* __restrict__ bo,
    const float* __restrict__ ln2_w, const float* __restrict__ ln2_b,
    const float* __restrict__ w1,    const float* __restrict__ b1,
    const float* __restrict__ w2,    const float* __restrict__ b2,
    float* __restrict__ out)
{
    // per block: 2 batches. Per batch: 64 key-pairs x 24 floats (kA0,kB0,...,vA5,vB5)
    __shared__ float s_kv[2 * 64 * 24];   // 12 KB
    __shared__ float s_w[276];

    float* s_wqkv = s_w;          // 108
    float* s_bqkv = s_w + 108;    // 18
    float* s_wo   = s_w + 126;    // 36
    float* s_bo   = s_w + 162;    // 6
    float* s_w1   = s_w + 168;    // 36
    float* s_b1   = s_w + 204;    // 6
    float* s_w2   = s_w + 210;    // 36
    float* s_b2   = s_w + 246;    // 6
    float* s_l1w  = s_w + 252;    // 6
    float* s_l1b  = s_w + 258;    // 6
    float* s_l2w  = s_w + 264;    // 6
    float* s_l2b  = s_w + 270;    // 6

    const int t    = threadIdx.x;
    const int half = t >> 6;          // which batch within the block
    const int u    = t & 63;          // query-pair index: tokens 2u, 2u+1
    const int batch = blockIdx.x * 2 + half;

    // ---- stage weights ----
    if (t < 108) s_wqkv[t] = wqkv[t];
    if (t < 18)  s_bqkv[t] = bqkv[t];
    if (t < 36) { s_wo[t] = wo[t]; s_w1[t] = w1[t]; s_w2[t] = w2[t]; }
    if (t < DD) {
        s_bo[t] = bo[t]; s_b1[t] = b1[t]; s_b2[t] = b2[t];
        s_l1w[t] = ln1_w[t]; s_l1b[t] = ln1_b[t];
        s_l2w[t] = ln2_w[t]; s_l2b[t] = ln2_b[t];
    }

    // ---- load x for my two tokens (12 contiguous floats, 16B aligned) ----
    const long base = ((long)batch * SEQ + 2 * u) * DD;
    float xv[12];
    {
        const float4* xp = (const float4*)(x + base);
        float4 X0 = xp[0], X1 = xp[1], X2 = xp[2];
        xv[0] = X0.x; xv[1] = X0.y; xv[2]  = X0.z; xv[3]  = X0.w;
        xv[4] = X1.x; xv[5] = X1.y; xv[6]  = X1.z; xv[7]  = X1.w;
        xv[8] = X2.x; xv[9] = X2.y; xv[10] = X2.z; xv[11] = X2.w;
    }

    // ---- LN1 stats (no smem needed yet) ----
    float mA = 0.f, mB = 0.f;
#pragma unroll
    for (int j = 0; j < DD; ++j) { mA += xv[j]; mB += xv[6 + j]; }
    mA *= (1.f / DD); mB *= (1.f / DD);
    float vA = 0.f, vB = 0.f;
#pragma unroll
    for (int j = 0; j < DD; ++j) {
        float dA = xv[j] - mA;     vA = fmaf(dA, dA, vA);
        float dB = xv[6 + j] - mB; vB = fmaf(dB, dB, vB);
    }
    float rA = rsqrtf(vA * (1.f / DD) + 1e-5f);
    float rB = rsqrtf(vB * (1.f / DD) + 1e-5f);

    __syncthreads();   // weights staged

    float hA[DD], hB[DD];
#pragma unroll
    for (int j = 0; j < DD; ++j) {
        hA[j] = fmaf((xv[j] - mA) * rA,     s_l1w[j], s_l1b[j]);
        hB[j] = fmaf((xv[6 + j] - mB) * rB, s_l1w[j], s_l1b[j]);
    }

    // ---- QKV projection for both tokens ----
    // fold 1/sqrt(D) * log2(e) into q so softmax uses raw ex2
    const float SCL = 0.58897934f;
    u64 qa2[DD], qb2[DD];
#pragma unroll
    for (int j = 0; j < DD; ++j) {
        float a = s_bqkv[j], b = s_bqkv[j];
#pragma unroll
        for (int i = 0; i < DD; ++i) {
            a = fmaf(hA[i], s_wqkv[i * 18 + j], a);
            b = fmaf(hB[i], s_wqkv[i * 18 + j], b);
        }
        a *= SCL; b *= SCL;
        qa2[j] = pack2(a, a);
        qb2[j] = pack2(b, b);
    }
    float kvA[12], kvB[12];
#pragma unroll
    for (int j = 0; j < 12; ++j) {
        float a = s_bqkv[6 + j], b = s_bqkv[6 + j];
#pragma unroll
        for (int i = 0; i < DD; ++i) {
            a = fmaf(hA[i], s_wqkv[i * 18 + 6 + j], a);
            b = fmaf(hB[i], s_wqkv[i * 18 + 6 + j], b);
        }
        kvA[j] = a; kvB[j] = b;
    }
    // interleave by key pair: [2m] = token 2u, [2m+1] = token 2u+1
    {
        float4* pp = (float4*)(s_kv + (half * 64 + u) * 24);
#pragma unroll
        for (int i = 0; i < 6; ++i)
            pp[i] = make_float4(kvA[2 * i], kvB[2 * i], kvA[2 * i + 1], kvB[2 * i + 1]);
    }

    __syncthreads();   // all K/V visible

    // ---- causal attention: queries (2u, 2u+1), keys in pairs, f32x2 lanes = key pair ----
    const ulonglong2* kvb = (const ulonglong2*)(s_kv + half * 64 * 24);
    u64 acca[DD], accb[DD];
#pragma unroll
    for (int d = 0; d < DD; ++d) { acca[d] = 0ull; accb[d] = 0ull; }
    u64 la2 = 0ull, lb2 = 0ull;

#pragma unroll 2
    for (int j = 0; j < u; ++j) {
        const ulonglong2* p = kvb + j * 6;
        ulonglong2 K0 = p[0], K1 = p[1], K2 = p[2];
        ulonglong2 V0 = p[3], V1 = p[4], V2 = p[5];
        u64 sa = dot6(qa2, K0, K1, K2);
        u64 sb = dot6(qb2, K0, K1, K2);
        float saA, saB, sbA, sbB;
        unpack2(sa, saA, saB); unpack2(sb, sbA, sbB);
        u64 pa = pack2(ex2f(saA), ex2f(saB));
        u64 pb = pack2(ex2f(sbA), ex2f(sbB));
        la2 = fadd2(la2, pa); lb2 = fadd2(lb2, pb);
        acca[0] = ffma2(pa, V0.x, acca[0]); accb[0] = ffma2(pb, V0.x, accb[0]);
        acca[1] = ffma2(pa, V0.y, acca[1]); accb[1] = ffma2(pb, V0.y, accb[1]);
        acca[2] = ffma2(pa, V1.x, acca[2]); accb[2] = ffma2(pb, V1.x, accb[2]);
        acca[3] = ffma2(pa, V1.y, acca[3]); accb[3] = ffma2(pb, V1.y, accb[3]);
        acca[4] = ffma2(pa, V2.x, acca[4]); accb[4] = ffma2(pb, V2.x, accb[4]);
        acca[5] = ffma2(pa, V2.y, acca[5]); accb[5] = ffma2(pb, V2.y, accb[5]);
    }
    // diagonal key pair (tokens 2u, 2u+1): query 2u must mask key 2u+1
    {
        const ulonglong2* p = kvb + u * 6;
        ulonglong2 K0 = p[0], K1 = p[1], K2 = p[2];
        ulonglong2 V0 = p[3], V1 = p[4], V2 = p[5];
        u64 sa = dot6(qa2, K0, K1, K2);
        u64 sb = dot6(qb2, K0, K1, K2);
        float saA, saB, sbA, sbB;
        unpack2(sa, saA, saB); unpack2(sb, sbA, sbB);
        (void)saB;
        u64 pa = pack2(ex2f(saA), 0.0f);
        u64 pb = pack2(ex2f(sbA), ex2f(sbB));
        la2 = fadd2(la2, pa); lb2 = fadd2(lb2, pb);
        acca[0] = ffma2(pa, V0.x, acca[0]); accb[0] = ffma2(pb, V0.x, accb[0]);
        acca[1] = ffma2(pa, V0.y, acca[1]); accb[1] = ffma2(pb, V0.y, accb[1]);
        acca[2] = ffma2(pa, V1.x, acca[2]); accb[2] = ffma2(pb, V1.x, accb[2]);
        acca[3] = ffma2(pa, V1.y, acca[3]); accb[3] = ffma2(pb, V1.y, accb[3]);
        acca[4] = ffma2(pa, V2.x, acca[4]); accb[4] = ffma2(pb, V2.x, accb[4]);
        acca[5] = ffma2(pa, V2.y, acca[5]); accb[5] = ffma2(pb, V2.y, accb[5]);
    }

    float lo, hi;
    unpack2(la2, lo, hi); float la = lo + hi;
    unpack2(lb2, lo, hi); float lb = lo + hi;
    float inva = rcpf(la), invb = rcpf(lb);
    float oA[DD], oB[DD];
#pragma unroll
    for (int d = 0; d < DD; ++d) {
        unpack2(acca[d], lo, hi); oA[d] = (lo + hi) * inva;
        unpack2(accb[d], lo, hi); oB[d] = (lo + hi) * invb;
    }

    // ---- epilogue for both tokens, vectorized store ----
    float outv[12];
    epilogue(oA, xv,     s_wo, s_bo, s_l2w, s_l2b, s_w1, s_b1, s_w2, s_b2, outv);
    epilogue(oB, xv + 6, s_wo, s_bo, s_l2w, s_l2b, s_w1, s_b1, s_w2, s_b2, outv + 6);
    {
        float4* op = (float4*)(out + base);
        op[0] = make_float4(outv[0], outv[1], outv[2],  outv[3]);
        op[1] = make_float4(outv[4], outv[5], outv[6],  outv[7]);
        op[2] = make_float4(outv[8], outv[9], outv[10], outv[11]);
    }
}

extern "C" void kernel_launch(void* const* d_in, const int* in_sizes, int n_in,
                              void* d_out, int out_size) {
    const float* x     = (const float*)d_in[0];
    const float* ln1_w = (const float*)d_in[1];
    const float* ln1_b = (const float*)d_in[2];
    const float* wqkv  = (const float*)d_in[3];
    const float* bqkv  = (const float*)d_in[4];
    const float* wo    = (const float*)d_in[5];
    const float* bo    = (const float*)d_in[6];
    const float* ln2_w = (const float*)d_in[7];
    const float* ln2_b = (const float*)d_in[8];
    const float* w1    = (const float*)d_in[9];
    const float* b1    = (const float*)d_in[10];
    const float* w2    = (const float*)d_in[11];
    const float* b2    = (const float*)d_in[12];
    float* out = (float*)d_out;

    const int B = in_sizes[0] / (SEQ * DD);   // 8192
    block_ffn_kernel<<<B / 2, 128>>>(x, ln1_w, ln1_b, wqkv, bqkv, wo, bo,
                                     ln2_w, ln2_b, w1, b1, w2, b2, out);
}

// round 6
// speedup vs baseline: 1.2573x; 1.1247x over previous
#include <cuda_runtime.h>
#include <math.h>

#define DD 6
#define SEQ 128
typedef unsigned long long u64;

// per-batch K/V region: 64 pairs * 24 floats = 1536, +4 pad so the 4 batch
// bases land in distinct 16B bank-quads (1540 mod 32 words = 4 -> quad b)
#define KV_STRIDE 1540

__device__ __forceinline__ u64 pack2(float lo, float hi) {
    u64 r; asm("mov.b64 %0, {%1, %2};" : "=l"(r) : "f"(lo), "f"(hi)); return r;
}
__device__ __forceinline__ void unpack2(u64 v, float& lo, float& hi) {
    asm("mov.b64 {%0, %1}, %2;" : "=f"(lo), "=f"(hi) : "l"(v));
}
__device__ __forceinline__ u64 ffma2(u64 a, u64 b, u64 c) {
    u64 d; asm("fma.rn.f32x2 %0, %1, %2, %3;" : "=l"(d) : "l"(a), "l"(b), "l"(c)); return d;
}
__device__ __forceinline__ u64 fmul2(u64 a, u64 b) {
    u64 d; asm("mul.rn.f32x2 %0, %1, %2;" : "=l"(d) : "l"(a), "l"(b)); return d;
}
__device__ __forceinline__ u64 fadd2(u64 a, u64 b) {
    u64 d; asm("add.rn.f32x2 %0, %1, %2;" : "=l"(d) : "l"(a), "l"(b)); return d;
}
__device__ __forceinline__ float ex2f(float x) {
    float y; asm("ex2.approx.f32 %0, %1;" : "=f"(y) : "f"(x)); return y;
}
__device__ __forceinline__ float rcpf(float x) {
    float y; asm("rcp.approx.f32 %0, %1;" : "=f"(y) : "f"(x)); return y;
}

__device__ __forceinline__ u64 dot6(const u64* q, ulonglong2 K0, ulonglong2 K1, ulonglong2 K2) {
    return ffma2(q[0], K0.x,
           ffma2(q[1], K0.y,
           ffma2(q[2], K1.x,
           ffma2(q[3], K1.y,
           ffma2(q[4], K2.x,
           fmul2(q[5], K2.y))))));
}

// out-proj + residual + LN2 + FFN + residual for one token
__device__ __forceinline__ void epilogue(
    const float* o, const float* xv,
    const float* s_wo, const float* s_bo,
    const float* s_l2w, const float* s_l2b,
    const float* s_w1, const float* s_b1,
    const float* s_w2, const float* s_b2,
    float* res)
{
    float y[DD];
#pragma unroll
    for (int d = 0; d < DD; ++d) {
        float a = s_bo[d];
#pragma unroll
        for (int i = 0; i < DD; ++i) a = fmaf(o[i], s_wo[i * 6 + d], a);
        y[d] = xv[d] + a;
    }
    float m = 0.f;
#pragma unroll
    for (int d = 0; d < DD; ++d) m += y[d];
    m *= (1.f / DD);
    float v = 0.f;
#pragma unroll
    for (int d = 0; d < DD; ++d) { float t = y[d] - m; v = fmaf(t, t, v); }
    float r = rsqrtf(v * (1.f / DD) + 1e-5f);
    float h2[DD];
#pragma unroll
    for (int d = 0; d < DD; ++d)
        h2[d] = fmaf((y[d] - m) * r, s_l2w[d], s_l2b[d]);
    float g[DD];
#pragma unroll
    for (int d = 0; d < DD; ++d) {
        float a = s_b1[d];
#pragma unroll
        for (int i = 0; i < DD; ++i) a = fmaf(h2[i], s_w1[i * 6 + d], a);
        g[d] = a * normcdff(a);           // exact gelu
    }
#pragma unroll
    for (int d = 0; d < DD; ++d) {
        float a = s_b2[d];
#pragma unroll
        for (int i = 0; i < DD; ++i) a = fmaf(g[i], s_w2[i * 6 + d], a);
        res[d] = y[d] + a;
    }
}

__global__ __launch_bounds__(256, 2) void block_ffn_kernel(
    const float* __restrict__ x,
    const float* __restrict__ ln1_w, const float* __restrict__ ln1_b,
    const float* __restrict__ wqkv,  const float* __restrict__ bqkv,
    const float* __restrict__ wo,    const float* __restrict__ bo,
    const float* __restrict__ ln2_w, const float* __restrict__ ln2_b,
    const float* __restrict__ w1,    const float* __restrict__ b1,
    const float* __restrict__ w2,    const float* __restrict__ b2,
    float* __restrict__ out)
{
    // 4 batches per block; per batch 64 key-pairs x 24 floats, pair-interleaved
    __shared__ float s_kv[4 * KV_STRIDE];   // ~24.6 KB
    __shared__ float s_w[276];

    float* s_wqkv = s_w;          // 108
    float* s_bqkv = s_w + 108;    // 18
    float* s_wo   = s_w + 126;    // 36
    float* s_bo   = s_w + 162;    // 6
    float* s_w1   = s_w + 168;    // 36
    float* s_b1   = s_w + 204;    // 6
    float* s_w2   = s_w + 210;    // 36
    float* s_b2   = s_w + 246;    // 6
    float* s_l1w  = s_w + 252;    // 6
    float* s_l1b  = s_w + 258;    // 6
    float* s_l2w  = s_w + 264;    // 6
    float* s_l2b  = s_w + 270;    // 6

    const int t = threadIdx.x;
    const int b = t & 3;              // batch slot within block
    const int u = t >> 2;             // query-pair index: tokens 2u, 2u+1
    const int batch = blockIdx.x * 4 + b;

    // ---- stage weights ----
    if (t < 108) s_wqkv[t] = wqkv[t];
    if (t < 18)  s_bqkv[t] = bqkv[t];
    if (t < 36) { s_wo[t] = wo[t]; s_w1[t] = w1[t]; s_w2[t] = w2[t]; }
    if (t < DD) {
        s_bo[t] = bo[t]; s_b1[t] = b1[t]; s_b2[t] = b2[t];
        s_l1w[t] = ln1_w[t]; s_l1b[t] = ln1_b[t];
        s_l2w[t] = ln2_w[t]; s_l2b[t] = ln2_b[t];
    }

    const long base = ((long)batch * SEQ + 2 * u) * DD;

    // ---- LN1 for my two tokens (xv is NOT kept live across the loop) ----
    float hA[DD], hB[DD];
    {
        float xv[12];
        const float4* xp = (const float4*)(x + base);
        float4 X0 = xp[0], X1 = xp[1], X2 = xp[2];
        xv[0] = X0.x; xv[1] = X0.y; xv[2]  = X0.z; xv[3]  = X0.w;
        xv[4] = X1.x; xv[5] = X1.y; xv[6]  = X1.z; xv[7]  = X1.w;
        xv[8] = X2.x; xv[9] = X2.y; xv[10] = X2.z; xv[11] = X2.w;

        float mA = 0.f, mB = 0.f;
#pragma unroll
        for (int j = 0; j < DD; ++j) { mA += xv[j]; mB += xv[6 + j]; }
        mA *= (1.f / DD); mB *= (1.f / DD);
        float vA = 0.f, vB = 0.f;
#pragma unroll
        for (int j = 0; j < DD; ++j) {
            float dA = xv[j] - mA;     vA = fmaf(dA, dA, vA);
            float dB = xv[6 + j] - mB; vB = fmaf(dB, dB, vB);
        }
        float rA = rsqrtf(vA * (1.f / DD) + 1e-5f);
        float rB = rsqrtf(vB * (1.f / DD) + 1e-5f);

        __syncthreads();   // weights staged

#pragma unroll
        for (int j = 0; j < DD; ++j) {
            hA[j] = fmaf((xv[j] - mA) * rA,     s_l1w[j], s_l1b[j]);
            hB[j] = fmaf((xv[6 + j] - mB) * rB, s_l1w[j], s_l1b[j]);
        }
    }

    // ---- QKV projection; fold 1/sqrt(D)*log2(e) into q ----
    const float SCL = 0.58897934f;
    u64 qa2[DD], qb2[DD];
#pragma unroll
    for (int j = 0; j < DD; ++j) {
        float a = s_bqkv[j], bq = s_bqkv[j];
#pragma unroll
        for (int i = 0; i < DD; ++i) {
            a  = fmaf(hA[i], s_wqkv[i * 18 + j], a);
            bq = fmaf(hB[i], s_wqkv[i * 18 + j], bq);
        }
        a *= SCL; bq *= SCL;
        qa2[j] = pack2(a, a);
        qb2[j] = pack2(bq, bq);
    }
    {
        float kvA[12], kvB[12];
#pragma unroll
        for (int j = 0; j < 12; ++j) {
            float a = s_bqkv[6 + j], bq = s_bqkv[6 + j];
#pragma unroll
            for (int i = 0; i < DD; ++i) {
                a  = fmaf(hA[i], s_wqkv[i * 18 + 6 + j], a);
                bq = fmaf(hB[i], s_wqkv[i * 18 + 6 + j], bq);
            }
            kvA[j] = a; kvB[j] = bq;
        }
        // interleave by key pair: lanes = (token 2u, token 2u+1)
        float4* pp = (float4*)(s_kv + b * KV_STRIDE + u * 24);
#pragma unroll
        for (int i = 0; i < 6; ++i)
            pp[i] = make_float4(kvA[2 * i], kvB[2 * i], kvA[2 * i + 1], kvB[2 * i + 1]);
    }

    __syncthreads();   // all K/V visible

    // ---- causal attention ----
    const ulonglong2* kvb = (const ulonglong2*)(s_kv + b * KV_STRIDE);
    u64 acca[DD], accb[DD];
#pragma unroll
    for (int d = 0; d < DD; ++d) { acca[d] = 0ull; accb[d] = 0ull; }
    u64 la2 = 0ull, lb2 = 0ull;

#pragma unroll 2
    for (int j = 0; j < u; ++j) {
        const ulonglong2* p = kvb + j * 6;
        ulonglong2 K0 = p[0], K1 = p[1], K2 = p[2];
        ulonglong2 V0 = p[3], V1 = p[4], V2 = p[5];
        u64 sa = dot6(qa2, K0, K1, K2);
        u64 sb = dot6(qb2, K0, K1, K2);
        float saA, saB, sbA, sbB;
        unpack2(sa, saA, saB); unpack2(sb, sbA, sbB);
        u64 pa = pack2(ex2f(saA), ex2f(saB));
        u64 pb = pack2(ex2f(sbA), ex2f(sbB));
        la2 = fadd2(la2, pa); lb2 = fadd2(lb2, pb);
        acca[0] = ffma2(pa, V0.x, acca[0]); accb[0] = ffma2(pb, V0.x, accb[0]);
        acca[1] = ffma2(pa, V0.y, acca[1]); accb[1] = ffma2(pb, V0.y, accb[1]);
        acca[2] = ffma2(pa, V1.x, acca[2]); accb[2] = ffma2(pb, V1.x, accb[2]);
        acca[3] = ffma2(pa, V1.y, acca[3]); accb[3] = ffma2(pb, V1.y, accb[3]);
        acca[4] = ffma2(pa, V2.x, acca[4]); accb[4] = ffma2(pb, V2.x, accb[4]);
        acca[5] = ffma2(pa, V2.y, acca[5]); accb[5] = ffma2(pb, V2.y, accb[5]);
    }
    // diagonal key pair: query 2u masks key 2u+1
    {
        const ulonglong2* p = kvb + u * 6;
        ulonglong2 K0 = p[0], K1 = p[1], K2 = p[2];
        ulonglong2 V0 = p[3], V1 = p[4], V2 = p[5];
        u64 sa = dot6(qa2, K0, K1, K2);
        u64 sb = dot6(qb2, K0, K1, K2);
        float saA, saB, sbA, sbB;
        unpack2(sa, saA, saB); unpack2(sb, sbA, sbB);
        (void)saB;
        u64 pa = pack2(ex2f(saA), 0.0f);
        u64 pb = pack2(ex2f(sbA), ex2f(sbB));
        la2 = fadd2(la2, pa); lb2 = fadd2(lb2, pb);
        acca[0] = ffma2(pa, V0.x, acca[0]); accb[0] = ffma2(pb, V0.x, accb[0]);
        acca[1] = ffma2(pa, V0.y, acca[1]); accb[1] = ffma2(pb, V0.y, accb[1]);
        acca[2] = ffma2(pa, V1.x, acca[2]); accb[2] = ffma2(pb, V1.x, accb[2]);
        acca[3] = ffma2(pa, V1.y, acca[3]); accb[3] = ffma2(pb, V1.y, accb[3]);
        acca[4] = ffma2(pa, V2.x, acca[4]); accb[4] = ffma2(pb, V2.x, accb[4]);
        acca[5] = ffma2(pa, V2.y, acca[5]); accb[5] = ffma2(pb, V2.y, accb[5]);
    }

    float lo, hi;
    unpack2(la2, lo, hi); float la = lo + hi;
    unpack2(lb2, lo, hi); float lb = lo + hi;
    float inva = rcpf(la), invb = rcpf(lb);
    float oA[DD], oB[DD];
#pragma unroll
    for (int d = 0; d < DD; ++d) {
        unpack2(acca[d], lo, hi); oA[d] = (lo + hi) * inva;
        unpack2(accb[d], lo, hi); oB[d] = (lo + hi) * invb;
    }

    // ---- reload x (L2 hit; frees 12 regs across the hot loop) ----
    float xv[12];
    {
        const float4* xp = (const float4*)(x + base);
        float4 X0 = xp[0], X1 = xp[1], X2 = xp[2];
        xv[0] = X0.x; xv[1] = X0.y; xv[2]  = X0.z; xv[3]  = X0.w;
        xv[4] = X1.x; xv[5] = X1.y; xv[6]  = X1.z; xv[7]  = X1.w;
        xv[8] = X2.x; xv[9] = X2.y; xv[10] = X2.z; xv[11] = X2.w;
    }

    float outv[12];
    epilogue(oA, xv,     s_wo, s_bo, s_l2w, s_l2b, s_w1, s_b1, s_w2, s_b2, outv);
    epilogue(oB, xv + 6, s_wo, s_bo, s_l2w, s_l2b, s_w1, s_b1, s_w2, s_b2, outv + 6);
    {
        float4* op = (float4*)(out + base);
        op[0] = make_float4(outv[0], outv[1], outv[2],  outv[3]);
        op[1] = make_float4(outv[4], outv[5], outv[6],  outv[7]);
        op[2] = make_float4(outv[8], outv[9], outv[10], outv[11]);
    }
}

extern "C" void kernel_launch(void* const* d_in, const int* in_sizes, int n_in,
                              void* d_out, int out_size) {
    const float* x     = (const float*)d_in[0];
    const float* ln1_w = (const float*)d_in[1];
    const float* ln1_b = (const float*)d_in[2];
    const float* wqkv  = (const float*)d_in[3];
    const float* bqkv  = (const float*)d_in[4];
    const float* wo    = (const float*)d_in[5];
    const float* bo    = (const float*)d_in[6];
    const float* ln2_w = (const float*)d_in[7];
    const float* ln2_b = (const float*)d_in[8];
    const float* w1    = (const float*)d_in[9];
    const float* b1    = (const float*)d_in[10];
    const float* w2    = (const float*)d_in[11];
    const float* b2    = (const float*)d_in[12];
    float* out = (float*)d_out;

    const int B = in_sizes[0] / (SEQ * DD);   // 8192
    block_ffn_kernel<<<B / 4, 256>>>(x, ln1_w, ln1_b, wqkv, bqkv, wo, bo,
                                     ln2_w, ln2_b, w1, b1, w2, b2, out);
}